// round 14
// baseline (speedup 1.0000x reference)
#include <cuda_runtime.h>
#include <cuda_fp16.h>
#include <cstdint>
#include <math.h>

// ---------------- problem constants ----------------
#define B_    128
#define T_    512
#define PT_   16
#define SKIP_ 32
#define NSEQ  4096

// ---------------- device-global scratch ----------------
__device__ __half g_xp16[16u * 4096u * 512u];    // x packed fp16 (hi only)
__device__ __half g_wp16[1536u * 1024u];         // W packed hi|lo (gate-interleaved cols)
__device__ __half g_up16[1536u * 1024u];         // U packed hi|lo
__device__ float  g_hf[2][NSEQ * 512u];          // hidden fp32 ping-pong
__device__ __half g_hp16[2][NSEQ * 512u];        // hidden fp16 ping-pong

// ---------------- smem layout (per stage, KC=64, rows padded 128B->144B) ----------------
// A: 256 rows * 144 = 36864 ; Bhi: 96 * 144 = 13824 ; Blo: 13824
#define ROWB        144
#define OFF_BHI     36864
#define BLO_DELTA   13824
#define STAGE_BYTES 64512
#define SMEM_BYTES  (2 * STAGE_BYTES)    // 129024

// ---------------- helpers ----------------
__device__ __forceinline__ uint32_t smem_u32(const void* p) {
    uint32_t a;
    asm("{ .reg .u64 t; cvta.to.shared.u64 t, %1; cvt.u32.u64 %0, t; }" : "=r"(a) : "l"(p));
    return a;
}
__device__ __forceinline__ void cp_async16(uint32_t s, const void* g) {
    asm volatile("cp.async.cg.shared.global [%0], [%1], 16;" :: "r"(s), "l"(g) : "memory");
}
__device__ __forceinline__ void cp_commit() { asm volatile("cp.async.commit_group;" ::: "memory"); }
template <int N> __device__ __forceinline__ void cp_wait() { asm volatile("cp.async.wait_group %0;" :: "n"(N) : "memory"); }

__device__ __forceinline__ void ldm4(uint32_t addr, uint32_t* r) {
    asm volatile("ldmatrix.sync.aligned.m8n8.x4.shared.b16 {%0,%1,%2,%3}, [%4];"
                 : "=r"(r[0]), "=r"(r[1]), "=r"(r[2]), "=r"(r[3]) : "r"(addr));
}
__device__ __forceinline__ void mma16816(float* d, const uint32_t* a, const uint32_t* b) {
    asm volatile("mma.sync.aligned.m16n8k16.row.col.f32.f16.f16.f32 "
                 "{%0,%1,%2,%3},{%4,%5,%6,%7},{%8,%9},{%0,%1,%2,%3};"
                 : "+f"(d[0]), "+f"(d[1]), "+f"(d[2]), "+f"(d[3])
                 : "r"(a[0]), "r"(a[1]), "r"(a[2]), "r"(a[3]), "r"(b[0]), "r"(b[1]));
}
__device__ __forceinline__ float sigmoidf_(float x) { return 1.f / (1.f + __expf(-x)); }

// ---------------- pack kernels ----------------
__global__ __launch_bounds__(256) void pack_wu16(const float* __restrict__ W, const float* __restrict__ U,
                                                 __half* __restrict__ Wp, __half* __restrict__ Up) {
    int idx = blockIdx.x * 256 + threadIdx.x;
    const float* S = blockIdx.y ? U : W;
    __half* D = blockIdx.y ? Up : Wp;
    int pr = idx >> 6;
    int k0 = (idx & 63) * 8;
    int jt = pr / 96;
    int q  = pr - jt * 96;
    int half_ = q / 48;
    int q2 = q - half_ * 48;
    int g  = q2 >> 4;
    int nn = q2 & 15;
    int col = g * 512 + jt * 32 + half_ * 16 + nn;
    __align__(16) __half hi[8], lo[8];
#pragma unroll
    for (int i = 0; i < 8; ++i) {
        float v = S[(size_t)(k0 + i) * 1536 + col];
        __half h = __float2half_rn(v);
        hi[i] = h;
        lo[i] = __float2half_rn(v - __half2float(h));
    }
    *(uint4*)(D + (size_t)pr * 1024 + k0)       = *(const uint4*)hi;
    *(uint4*)(D + (size_t)pr * 1024 + 512 + k0) = *(const uint4*)lo;
}

__global__ __launch_bounds__(256) void pack_x16(const float* __restrict__ x, __half* __restrict__ Xp) {
    unsigned idx = blockIdx.x * 256 + threadIdx.x;
    unsigned t   = idx >> 18;
    unsigned rem = idx & 0x3FFFFu;
    unsigned m   = rem >> 6;
    unsigned k0  = (rem & 63) * 8;
    unsigned bb  = m >> 5, kk = m & 31;
    const float* src = x + ((size_t)bb * T_ + (size_t)(t * SKIP_ + kk)) * 512 + k0;
    float4 v0 = *(const float4*)(src);
    float4 v1 = *(const float4*)(src + 4);
    float f[8] = {v0.x, v0.y, v0.z, v0.w, v1.x, v1.y, v1.z, v1.w};
    __align__(16) __half hi[8];
#pragma unroll
    for (int i = 0; i < 8; ++i) hi[i] = __float2half_rn(f[i]);
    __half* dst = Xp + ((size_t)t * 4096 + m) * 512;
    *(uint4*)(dst + k0) = *(const uint4*)hi;
}

// ---------------- loader (KC=64 stage, A=256 rows): 3584 chunks, 14/thread ----------------
__device__ __forceinline__ void load_stage(uint32_t stg, const __half* __restrict__ Arow,
                                           const __half* __restrict__ Bm, int jt, int k0, int tid) {
#pragma unroll
    for (int i = 0; i < 8; ++i) {           // A: 256 rows x 8 chunks = 2048
        int a = tid + i * 256;
        int row = a >> 3;
        int c   = a & 7;
        cp_async16(stg + row * ROWB + c * 16, Arow + (size_t)row * 512 + k0 + c * 8);
    }
#pragma unroll
    for (int i = 0; i < 6; ++i) {           // B hi+lo: 1536
        int b = tid + i * 256;
        int hilo = (b >= 768) ? 1 : 0;
        int idx  = b - hilo * 768;
        int row  = idx >> 3;
        int c    = idx & 7;
        cp_async16(stg + OFF_BHI + hilo * BLO_DELTA + row * ROWB + c * 16,
                   Bm + (size_t)(jt * 96 + row) * 1024 + hilo * 512 + k0 + c * 8);
    }
}

// 24 independent-accumulator MMAs for one B term (mi=4)
#define DO_TERM(BT, HACC)                                              \
    do {                                                               \
        _Pragma("unroll")                                              \
        for (int mi = 0; mi < 4; ++mi)                                 \
            _Pragma("unroll")                                          \
            for (int nj = 0; nj < 2; ++nj)                             \
                mma16816(dz[mi][nj], A4[mi], &BT[0][nj * 2]);          \
        _Pragma("unroll")                                              \
        for (int mi = 0; mi < 4; ++mi)                                 \
            _Pragma("unroll")                                          \
            for (int nj = 0; nj < 2; ++nj)                             \
                mma16816(dr[mi][nj], A4[mi], &BT[1][nj * 2]);          \
        _Pragma("unroll")                                              \
        for (int mi = 0; mi < 4; ++mi)                                 \
            _Pragma("unroll")                                          \
            for (int nj = 0; nj < 2; ++nj)                             \
                mma16816(HACC[mi][nj], A4[mi], &BT[2][nj * 2]);        \
    } while (0)

#define STAGE_MMA(HACC)                                                            \
    do {                                                                           \
        _Pragma("unroll")                                                          \
        for (int k16 = 0; k16 < 4; ++k16) {                                        \
            uint32_t ah = stg + aoff + k16 * 32;                                   \
            uint32_t bh = stg + OFF_BHI + boff + k16 * 32;                         \
            uint32_t bl = bh + BLO_DELTA;                                          \
            uint32_t A4[4][4], BH[3][4], BL[3][4];                                 \
            ldm4(ah, A4[0]);  ldm4(ah + 16 * ROWB, A4[1]);                         \
            ldm4(ah + 32 * ROWB, A4[2]);  ldm4(ah + 48 * ROWB, A4[3]);             \
            ldm4(bh, BH[0]);  ldm4(bh + 16 * ROWB, BH[1]);  ldm4(bh + 32 * ROWB, BH[2]); \
            ldm4(bl, BL[0]);  ldm4(bl + 16 * ROWB, BL[1]);  ldm4(bl + 32 * ROWB, BL[2]); \
            DO_TERM(BH, HACC);                                                     \
            DO_TERM(BL, HACC);                                                     \
        }                                                                          \
    } while (0)

// ---------------- fully fused GRU step, CTA tile 256x96 ----------------
__global__ __launch_bounds__(256, 1) void gru_fused(
    const __half* __restrict__ Xt,
    const __half* __restrict__ Wp,
    const __half* __restrict__ Up,
    const float* __restrict__ bias,
    const __half* __restrict__ hpack_in,
    const float* __restrict__ hprev,
    float* __restrict__ hout,
    __half* __restrict__ hpk,
    int first, int last)
{
    extern __shared__ __align__(16) char smem[];
    uint32_t sb = smem_u32(smem);
    const int tid  = threadIdx.x;
    const int lane = tid & 31;
    const int wid  = tid >> 5;
    const int wm   = wid >> 1;       // 0..3: 64-row slab
    const int wn   = wid & 1;        // 0..1: 48 B-rows
    const int jt   = blockIdx.x;     // 0..15
    const int mt   = blockIdx.y;     // 0..15

    float dz[4][2][4], dr[4][2][4], dxh[4][2][4], drh[4][2][4];
#pragma unroll
    for (int a = 0; a < 4; ++a)
#pragma unroll
        for (int b = 0; b < 2; ++b)
#pragma unroll
            for (int c = 0; c < 4; ++c) {
                dz[a][b][c] = 0.f; dr[a][b][c] = 0.f;
                dxh[a][b][c] = 0.f; drh[a][b][c] = 0.f;
            }

    const __half* ArowX = Xt + (size_t)mt * 256 * 512;
    const __half* ArowH = hpack_in + (size_t)mt * 256 * 512;

    load_stage(sb, ArowX, Wp, jt, 0, tid);
    cp_commit();

    const uint32_t aoff = (uint32_t)((wm * 64 + (lane & 15)) * ROWB + (lane >> 4) * 16);
    const uint32_t boff = (uint32_t)((wn * 48 + (lane & 7) + ((lane >> 4) << 3)) * ROWB + ((lane >> 3) & 1) * 16);

    // ---------------- phase 0: x_t @ W ----------------
#pragma unroll 2
    for (int s = 0; s < 8; ++s) {
        if (s < 7) {
            load_stage(sb + ((s + 1) & 1) * STAGE_BYTES, ArowX, Wp, jt, (s + 1) * 64, tid);
            cp_commit();
            cp_wait<1>();
        } else if (!first) {
            load_stage(sb + ((s + 1) & 1) * STAGE_BYTES, ArowH, Up, jt, 0, tid);
            cp_commit();
            cp_wait<1>();
        } else {
            cp_wait<0>();
        }
        __syncthreads();
        uint32_t stg = sb + (s & 1) * STAGE_BYTES;
        STAGE_MMA(dxh);
        __syncthreads();
    }

    // ---------------- phase 1: h @ U ----------------
    if (!first) {
#pragma unroll 2
        for (int s = 0; s < 8; ++s) {
            if (s < 7) {
                load_stage(sb + ((s + 1) & 1) * STAGE_BYTES, ArowH, Up, jt, (s + 1) * 64, tid);
                cp_commit();
                cp_wait<1>();
            } else {
                cp_wait<0>();
            }
            __syncthreads();
            uint32_t stg = sb + (s & 1) * STAGE_BYTES;
            STAGE_MMA(drh);
            __syncthreads();
        }
    }

    // ---------------- gate epilogue ----------------
#pragma unroll
    for (int mi = 0; mi < 4; ++mi)
#pragma unroll
        for (int rh = 0; rh < 2; ++rh) {
            int mg = mt * 256 + wm * 64 + mi * 16 + (lane >> 2) + rh * 8;
#pragma unroll
            for (int nj = 0; nj < 2; ++nj) {
                int cb   = nj * 8 + (lane & 3) * 2;
                int colh = jt * 32 + wn * 16 + cb;
                float2 hp = make_float2(0.f, 0.f);
                if (!first) hp = *(const float2*)(hprev + (size_t)mg * 512 + colh);
                float2 b0z = *(const float2*)(bias + colh);
                float2 b1z = *(const float2*)(bias + 1536 + colh);
                float2 b0r = *(const float2*)(bias + 512 + colh);
                float2 b1r = *(const float2*)(bias + 2048 + colh);
                float2 b0h = *(const float2*)(bias + 1024 + colh);
                float2 b1h = *(const float2*)(bias + 2560 + colh);
                float hpv[2] = {hp.x, hp.y};
                float b0zv[2] = {b0z.x, b0z.y}, b1zv[2] = {b1z.x, b1z.y};
                float b0rv[2] = {b0r.x, b0r.y}, b1rv[2] = {b1r.x, b1r.y};
                float b0hv[2] = {b0h.x, b0h.y}, b1hv[2] = {b1h.x, b1h.y};
                float hn[2];
#pragma unroll
                for (int cc = 0; cc < 2; ++cc) {
                    int r = rh * 2 + cc;
                    float zp  = dz[mi][nj][r] + b0zv[cc] + b1zv[cc];
                    float rp  = dr[mi][nj][r] + b0rv[cc] + b1rv[cc];
                    float xhp = dxh[mi][nj][r] + b0hv[cc];
                    float rhp = drh[mi][nj][r] + b1hv[cc];
                    float z  = sigmoidf_(zp);
                    float rg = sigmoidf_(rp);
                    float hh = fmaxf(xhp + rg * rhp, 0.f);
                    hn[cc] = z * hpv[cc] + (1.f - z) * hh;
                }
                *(float2*)(hout + (size_t)mg * 512 + colh) = make_float2(hn[0], hn[1]);
                if (!last)
                    *(__half2*)(hpk + (size_t)mg * 512 + colh) =
                        __halves2half2(__float2half_rn(hn[0]), __float2half_rn(hn[1]));
            }
        }
}

// ---------------- host ----------------
extern "C" void kernel_launch(void* const* d_in, const int* in_sizes, int n_in,
                              void* d_out, int out_size) {
    const float* x = (const float*)d_in[0];
    const float* W = (const float*)d_in[1];
    const float* U = (const float*)d_in[2];
    const float* b = (const float*)d_in[3];
    float* out = (float*)d_out;

    __half *Xp, *Wp, *Up, *Hp0;
    float *Hf0;
    cudaGetSymbolAddress((void**)&Xp, g_xp16);
    cudaGetSymbolAddress((void**)&Wp, g_wp16);
    cudaGetSymbolAddress((void**)&Up, g_up16);
    cudaGetSymbolAddress((void**)&Hf0, g_hf);
    cudaGetSymbolAddress((void**)&Hp0, g_hp16);
    float*  Hf[2] = {Hf0, Hf0 + (size_t)NSEQ * 512};
    __half* Hp[2] = {Hp0, Hp0 + (size_t)NSEQ * 512};

    static int smem_set = 0;
    if (!smem_set) {
        cudaFuncSetAttribute(gru_fused, cudaFuncAttributeMaxDynamicSharedMemorySize, SMEM_BYTES);
        smem_set = 1;
    }

    pack_wu16<<<dim3(384, 2), 256>>>(W, U, Wp, Up);
    pack_x16<<<16384, 256>>>(x, Xp);

    for (int t = 0; t < PT_; ++t) {
        const __half* Xt   = Xp + (size_t)t * 4096u * 512u;
        const __half* Ahp  = Hp[(t + 1) & 1];
        const float* hprev = Hf[(t + 1) & 1];
        float* ho = (t == PT_ - 1) ? out : Hf[t & 1];
        gru_fused<<<dim3(16, 16), 256, SMEM_BYTES>>>(
            Xt, Wp, Up, b, Ahp, hprev, ho, Hp[t & 1],
            t == 0 ? 1 : 0, t == PT_ - 1 ? 1 : 0);
    }
    (void)in_sizes; (void)n_in; (void)out_size;
}

// round 15
// speedup vs baseline: 1.1106x; 1.1106x over previous
#include <cuda_runtime.h>
#include <cuda_fp16.h>
#include <cstdint>
#include <math.h>

// ---------------- problem constants ----------------
#define B_    128
#define T_    512
#define PT_   16
#define SKIP_ 32
#define NSEQ  4096

// ---------------- device-global scratch ----------------
__device__ __half g_xp16[16u * 4096u * 512u];    // x packed fp16
__device__ __half g_wp16[1536u * 512u];          // W packed fp16 (gate-interleaved cols)
__device__ __half g_up16[1536u * 512u];          // U packed fp16
__device__ float  g_hf[2][NSEQ * 512u];          // hidden fp32 ping-pong
__device__ __half g_hp16[2][NSEQ * 512u];        // hidden fp16 ping-pong

// ---------------- smem layout (per stage, KC=64, rows padded 128B->144B) ----------------
// A: 128 rows * 144 = 18432 ; B: 96 * 144 = 13824
#define ROWB        144
#define OFF_B       18432
#define STAGE_BYTES 32256
#define SMEM_BYTES  (2 * STAGE_BYTES)    // 64512

// ---------------- helpers ----------------
__device__ __forceinline__ uint32_t smem_u32(const void* p) {
    uint32_t a;
    asm("{ .reg .u64 t; cvta.to.shared.u64 t, %1; cvt.u32.u64 %0, t; }" : "=r"(a) : "l"(p));
    return a;
}
__device__ __forceinline__ void cp_async16(uint32_t s, const void* g) {
    asm volatile("cp.async.cg.shared.global [%0], [%1], 16;" :: "r"(s), "l"(g) : "memory");
}
__device__ __forceinline__ void cp_commit() { asm volatile("cp.async.commit_group;" ::: "memory"); }
template <int N> __device__ __forceinline__ void cp_wait() { asm volatile("cp.async.wait_group %0;" :: "n"(N) : "memory"); }

__device__ __forceinline__ void ldm4(uint32_t addr, uint32_t* r) {
    asm volatile("ldmatrix.sync.aligned.m8n8.x4.shared.b16 {%0,%1,%2,%3}, [%4];"
                 : "=r"(r[0]), "=r"(r[1]), "=r"(r[2]), "=r"(r[3]) : "r"(addr));
}
__device__ __forceinline__ void mma16816(float* d, const uint32_t* a, const uint32_t* b) {
    asm volatile("mma.sync.aligned.m16n8k16.row.col.f32.f16.f16.f32 "
                 "{%0,%1,%2,%3},{%4,%5,%6,%7},{%8,%9},{%0,%1,%2,%3};"
                 : "+f"(d[0]), "+f"(d[1]), "+f"(d[2]), "+f"(d[3])
                 : "r"(a[0]), "r"(a[1]), "r"(a[2]), "r"(a[3]), "r"(b[0]), "r"(b[1]));
}
__device__ __forceinline__ float sigmoidf_(float x) { return 1.f / (1.f + __expf(-x)); }

// ---------------- pack kernels ----------------
// packed B row pr = jt*96 + half*48 + g*16 + nn  ->  natural col g*512 + jt*32 + half*16 + nn
__global__ __launch_bounds__(256) void pack_wu16(const float* __restrict__ W, const float* __restrict__ U,
                                                 __half* __restrict__ Wp, __half* __restrict__ Up) {
    int idx = blockIdx.x * 256 + threadIdx.x;        // 0..98303
    const float* S = blockIdx.y ? U : W;
    __half* D = blockIdx.y ? Up : Wp;
    int pr = idx >> 6;
    int k0 = (idx & 63) * 8;
    int jt = pr / 96;
    int q  = pr - jt * 96;
    int half_ = q / 48;
    int q2 = q - half_ * 48;
    int g  = q2 >> 4;
    int nn = q2 & 15;
    int col = g * 512 + jt * 32 + half_ * 16 + nn;
    __align__(16) __half hi[8];
#pragma unroll
    for (int i = 0; i < 8; ++i)
        hi[i] = __float2half_rn(S[(size_t)(k0 + i) * 1536 + col]);
    *(uint4*)(D + (size_t)pr * 512 + k0) = *(const uint4*)hi;
}

__global__ __launch_bounds__(256) void pack_x16(const float* __restrict__ x, __half* __restrict__ Xp) {
    unsigned idx = blockIdx.x * 256 + threadIdx.x;
    unsigned t   = idx >> 18;
    unsigned rem = idx & 0x3FFFFu;
    unsigned m   = rem >> 6;
    unsigned k0  = (rem & 63) * 8;
    unsigned bb  = m >> 5, kk = m & 31;
    const float* src = x + ((size_t)bb * T_ + (size_t)(t * SKIP_ + kk)) * 512 + k0;
    float4 v0 = *(const float4*)(src);
    float4 v1 = *(const float4*)(src + 4);
    float f[8] = {v0.x, v0.y, v0.z, v0.w, v1.x, v1.y, v1.z, v1.w};
    __align__(16) __half hi[8];
#pragma unroll
    for (int i = 0; i < 8; ++i) hi[i] = __float2half_rn(f[i]);
    __half* dst = Xp + ((size_t)t * 4096 + m) * 512;
    *(uint4*)(dst + k0) = *(const uint4*)hi;
}

// ---------------- loader (KC=64 stage): A 1024 + B 768 chunks, 7/thread ----------------
__device__ __forceinline__ void load_stage(uint32_t stg, const __half* __restrict__ Arow,
                                           const __half* __restrict__ Bm, int jt, int k0, int tid) {
#pragma unroll
    for (int i = 0; i < 4; ++i) {           // A: 128 rows x 8 chunks
        int a = tid + i * 256;
        int row = a >> 3;
        int c   = a & 7;
        cp_async16(stg + row * ROWB + c * 16, Arow + (size_t)row * 512 + k0 + c * 8);
    }
#pragma unroll
    for (int i = 0; i < 3; ++i) {           // B: 96 rows x 8 chunks
        int b = tid + i * 256;
        int row = b >> 3;
        int c   = b & 7;
        cp_async16(stg + OFF_B + row * ROWB + c * 16,
                   Bm + (size_t)(jt * 96 + row) * 512 + k0 + c * 8);
    }
}

// 12 independent-accumulator MMAs
#define DO_TERM(BT, HACC)                                              \
    do {                                                               \
        _Pragma("unroll")                                              \
        for (int mi = 0; mi < 2; ++mi)                                 \
            _Pragma("unroll")                                          \
            for (int nj = 0; nj < 2; ++nj)                             \
                mma16816(dz[mi][nj], A2[mi], &BT[0][nj * 2]);          \
        _Pragma("unroll")                                              \
        for (int mi = 0; mi < 2; ++mi)                                 \
            _Pragma("unroll")                                          \
            for (int nj = 0; nj < 2; ++nj)                             \
                mma16816(dr[mi][nj], A2[mi], &BT[1][nj * 2]);          \
        _Pragma("unroll")                                              \
        for (int mi = 0; mi < 2; ++mi)                                 \
            _Pragma("unroll")                                          \
            for (int nj = 0; nj < 2; ++nj)                             \
                mma16816(HACC[mi][nj], A2[mi], &BT[2][nj * 2]);        \
    } while (0)

#define STAGE_MMA(HACC)                                                            \
    do {                                                                           \
        _Pragma("unroll")                                                          \
        for (int k16 = 0; k16 < 4; ++k16) {                                        \
            uint32_t ah = stg + aoff + k16 * 32;                                   \
            uint32_t bh = stg + OFF_B + boff + k16 * 32;                           \
            uint32_t A2[2][4], BH[3][4];                                           \
            ldm4(ah, A2[0]);  ldm4(ah + 16 * ROWB, A2[1]);                         \
            ldm4(bh, BH[0]);  ldm4(bh + 16 * ROWB, BH[1]);  ldm4(bh + 32 * ROWB, BH[2]); \
            DO_TERM(BH, HACC);                                                     \
        }                                                                          \
    } while (0)

// ---------------- fully fused GRU step, CTA tile 128x96, plain fp16 ----------------
// K=1024 in two 8-stage phases: phase 0 x_t@W -> dz,dr,dxh ; phase 1 h@U -> dz,dr,drh
__global__ __launch_bounds__(256, 2) void gru_fused(
    const __half* __restrict__ Xt,
    const __half* __restrict__ Wp,
    const __half* __restrict__ Up,
    const float* __restrict__ bias,
    const __half* __restrict__ hpack_in,
    const float* __restrict__ hprev,
    float* __restrict__ hout,
    __half* __restrict__ hpk,
    int first, int last)
{
    extern __shared__ __align__(16) char smem[];
    uint32_t sb = smem_u32(smem);
    const int tid  = threadIdx.x;
    const int lane = tid & 31;
    const int wid  = tid >> 5;
    const int wm   = wid >> 1;
    const int wn   = wid & 1;
    const int jt   = blockIdx.x;
    const int mt   = blockIdx.y;

    float dz[2][2][4], dr[2][2][4], dxh[2][2][4], drh[2][2][4];
#pragma unroll
    for (int a = 0; a < 2; ++a)
#pragma unroll
        for (int b = 0; b < 2; ++b)
#pragma unroll
            for (int c = 0; c < 4; ++c) {
                dz[a][b][c] = 0.f; dr[a][b][c] = 0.f;
                dxh[a][b][c] = 0.f; drh[a][b][c] = 0.f;
            }

    const __half* ArowX = Xt + (size_t)mt * 128 * 512;
    const __half* ArowH = hpack_in + (size_t)mt * 128 * 512;

    load_stage(sb, ArowX, Wp, jt, 0, tid);
    cp_commit();

    const uint32_t aoff = (uint32_t)((wm * 32 + (lane & 15)) * ROWB + (lane >> 4) * 16);
    const uint32_t boff = (uint32_t)((wn * 48 + (lane & 7) + ((lane >> 4) << 3)) * ROWB + ((lane >> 3) & 1) * 16);

    // ---------------- phase 0: x_t @ W ----------------
#pragma unroll 2
    for (int s = 0; s < 8; ++s) {
        if (s < 7) {
            load_stage(sb + ((s + 1) & 1) * STAGE_BYTES, ArowX, Wp, jt, (s + 1) * 64, tid);
            cp_commit();
            cp_wait<1>();
        } else if (!first) {
            load_stage(sb + ((s + 1) & 1) * STAGE_BYTES, ArowH, Up, jt, 0, tid);
            cp_commit();
            cp_wait<1>();
        } else {
            cp_wait<0>();
        }
        __syncthreads();
        uint32_t stg = sb + (s & 1) * STAGE_BYTES;
        STAGE_MMA(dxh);
        __syncthreads();
    }

    // ---------------- phase 1: h @ U ----------------
    if (!first) {
#pragma unroll 2
        for (int s = 0; s < 8; ++s) {
            if (s < 7) {
                load_stage(sb + ((s + 1) & 1) * STAGE_BYTES, ArowH, Up, jt, (s + 1) * 64, tid);
                cp_commit();
                cp_wait<1>();
            } else {
                cp_wait<0>();
            }
            __syncthreads();
            uint32_t stg = sb + (s & 1) * STAGE_BYTES;
            STAGE_MMA(drh);
            __syncthreads();
        }
    }

    // ---------------- gate epilogue ----------------
#pragma unroll
    for (int mi = 0; mi < 2; ++mi)
#pragma unroll
        for (int rh = 0; rh < 2; ++rh) {
            int mg = mt * 128 + wm * 32 + mi * 16 + (lane >> 2) + rh * 8;
#pragma unroll
            for (int nj = 0; nj < 2; ++nj) {
                int cb   = nj * 8 + (lane & 3) * 2;
                int colh = jt * 32 + wn * 16 + cb;
                float2 hp = make_float2(0.f, 0.f);
                if (!first) hp = *(const float2*)(hprev + (size_t)mg * 512 + colh);
                float2 b0z = *(const float2*)(bias + colh);
                float2 b1z = *(const float2*)(bias + 1536 + colh);
                float2 b0r = *(const float2*)(bias + 512 + colh);
                float2 b1r = *(const float2*)(bias + 2048 + colh);
                float2 b0h = *(const float2*)(bias + 1024 + colh);
                float2 b1h = *(const float2*)(bias + 2560 + colh);
                float hpv[2] = {hp.x, hp.y};
                float b0zv[2] = {b0z.x, b0z.y}, b1zv[2] = {b1z.x, b1z.y};
                float b0rv[2] = {b0r.x, b0r.y}, b1rv[2] = {b1r.x, b1r.y};
                float b0hv[2] = {b0h.x, b0h.y}, b1hv[2] = {b1h.x, b1h.y};
                float hn[2];
#pragma unroll
                for (int cc = 0; cc < 2; ++cc) {
                    int r = rh * 2 + cc;
                    float zp  = dz[mi][nj][r] + b0zv[cc] + b1zv[cc];
                    float rp  = dr[mi][nj][r] + b0rv[cc] + b1rv[cc];
                    float xhp = dxh[mi][nj][r] + b0hv[cc];
                    float rhp = drh[mi][nj][r] + b1hv[cc];
                    float z  = sigmoidf_(zp);
                    float rg = sigmoidf_(rp);
                    float hh = fmaxf(xhp + rg * rhp, 0.f);
                    hn[cc] = z * hpv[cc] + (1.f - z) * hh;
                }
                *(float2*)(hout + (size_t)mg * 512 + colh) = make_float2(hn[0], hn[1]);
                if (!last)
                    *(__half2*)(hpk + (size_t)mg * 512 + colh) =
                        __halves2half2(__float2half_rn(hn[0]), __float2half_rn(hn[1]));
            }
        }
}

// ---------------- host ----------------
extern "C" void kernel_launch(void* const* d_in, const int* in_sizes, int n_in,
                              void* d_out, int out_size) {
    const float* x = (const float*)d_in[0];
    const float* W = (const float*)d_in[1];
    const float* U = (const float*)d_in[2];
    const float* b = (const float*)d_in[3];
    float* out = (float*)d_out;

    __half *Xp, *Wp, *Up, *Hp0;
    float *Hf0;
    cudaGetSymbolAddress((void**)&Xp, g_xp16);
    cudaGetSymbolAddress((void**)&Wp, g_wp16);
    cudaGetSymbolAddress((void**)&Up, g_up16);
    cudaGetSymbolAddress((void**)&Hf0, g_hf);
    cudaGetSymbolAddress((void**)&Hp0, g_hp16);
    float*  Hf[2] = {Hf0, Hf0 + (size_t)NSEQ * 512};
    __half* Hp[2] = {Hp0, Hp0 + (size_t)NSEQ * 512};

    static int smem_set = 0;
    if (!smem_set) {
        cudaFuncSetAttribute(gru_fused, cudaFuncAttributeMaxDynamicSharedMemorySize, SMEM_BYTES);
        smem_set = 1;
    }

    pack_wu16<<<dim3(384, 2), 256>>>(W, U, Wp, Up);
    pack_x16<<<16384, 256>>>(x, Xp);

    for (int t = 0; t < PT_; ++t) {
        const __half* Xt   = Xp + (size_t)t * 4096u * 512u;
        const __half* Ahp  = Hp[(t + 1) & 1];
        const float* hprev = Hf[(t + 1) & 1];
        float* ho = (t == PT_ - 1) ? out : Hf[t & 1];
        gru_fused<<<dim3(16, 32), 256, SMEM_BYTES>>>(
            Xt, Wp, Up, b, Ahp, hprev, ho, Hp[t & 1],
            t == 0 ? 1 : 0, t == PT_ - 1 ? 1 : 0);
    }
    (void)in_sizes; (void)n_in; (void)out_size;
}

// round 17
// speedup vs baseline: 2.0372x; 1.8344x over previous
#include <cuda_runtime.h>
#include <cuda_fp16.h>
#include <cstdint>
#include <math.h>

// ---------------- problem constants ----------------
#define B_    128
#define T_    512
#define PT_   16
#define SKIP_ 32
#define NSEQ  4096

// Blocked, pre-swizzled operand layouts:
//  A-blocks: 128 rows x 64 halves (16KB), SW128-swizzled, row pitch 128B
//  B-blocks:  96 rows x 64 halves (12KB), SW128-swizzled
#define BLK_A 8192u   // halves per A block
#define BLK_B 6144u   // halves per B block

__device__ __half g_xp16[16u * 32u * 8u * BLK_A];   // [t][mt][s] A blocks
__device__ __half g_wp16[16u * 8u * BLK_B];         // [jt][s] B blocks
__device__ __half g_up16[16u * 8u * BLK_B];
__device__ float  g_hf[2][NSEQ * 512u];             // hidden fp32 ping-pong
__device__ __half g_hp16[2][32u * 8u * BLK_A];      // hidden blocked ping-pong

// smem: 2 buffers x (A 16KB + B 12KB)
#define BUF_BYTES  28672
#define OFF_B      16384
#define SMEM_BYTES (2 * BUF_BYTES)   // 57344

#define SW(o) ((o) ^ ((((uint32_t)(o)) >> 3) & 0x70u))

// ---------------- helpers ----------------
__device__ __forceinline__ uint32_t smem_u32(const void* p) {
    uint32_t a;
    asm("{ .reg .u64 t; cvta.to.shared.u64 t, %1; cvt.u32.u64 %0, t; }" : "=r"(a) : "l"(p));
    return a;
}
__device__ __forceinline__ void mbar_init(uint32_t mb, uint32_t cnt) {
    asm volatile("mbarrier.init.shared.b64 [%0], %1;" :: "r"(mb), "r"(cnt) : "memory");
}
__device__ __forceinline__ void mbar_expect_tx(uint32_t mb, uint32_t bytes) {
    asm volatile("mbarrier.arrive.expect_tx.shared.b64 _, [%0], %1;" :: "r"(mb), "r"(bytes) : "memory");
}
__device__ __forceinline__ void bulk_g2s(uint32_t dst, const void* src, uint32_t bytes, uint32_t mb) {
    asm volatile("cp.async.bulk.shared::cta.global.mbarrier::complete_tx::bytes [%0], [%1], %2, [%3];"
                 :: "r"(dst), "l"(src), "r"(bytes), "r"(mb) : "memory");
}
__device__ __forceinline__ void mbar_wait(uint32_t mb, uint32_t parity) {
    asm volatile(
        "{\n\t.reg .pred P;\n\t"
        "W_%=:\n\t"
        "mbarrier.try_wait.parity.acquire.cta.shared::cta.b64 P, [%0], %1, 0x989680;\n\t"
        "@P bra.uni D_%=;\n\t"
        "bra.uni W_%=;\n\t"
        "D_%=:\n\t}"
        :: "r"(mb), "r"(parity) : "memory");
}
__device__ __forceinline__ void ldm4(uint32_t addr, uint32_t* r) {
    asm volatile("ldmatrix.sync.aligned.m8n8.x4.shared.b16 {%0,%1,%2,%3}, [%4];"
                 : "=r"(r[0]), "=r"(r[1]), "=r"(r[2]), "=r"(r[3]) : "r"(addr));
}
__device__ __forceinline__ void mma16816(float* d, const uint32_t* a, const uint32_t* b) {
    asm volatile("mma.sync.aligned.m16n8k16.row.col.f32.f16.f16.f32 "
                 "{%0,%1,%2,%3},{%4,%5,%6,%7},{%8,%9},{%0,%1,%2,%3};"
                 : "+f"(d[0]), "+f"(d[1]), "+f"(d[2]), "+f"(d[3])
                 : "r"(a[0]), "r"(a[1]), "r"(a[2]), "r"(a[3]), "r"(b[0]), "r"(b[1]));
}
__device__ __forceinline__ float sigmoidf_(float x) { return 1.f / (1.f + __expf(-x)); }

// ---------------- pack kernels (write blocked + swizzled) ----------------
// B packed row q = half*48 + g*16 + nn -> natural col g*512 + jt*32 + half*16 + nn
__global__ __launch_bounds__(256) void pack_wu16(const float* __restrict__ W, const float* __restrict__ U,
                                                 __half* __restrict__ Wp, __half* __restrict__ Up) {
    int idx = blockIdx.x * 256 + threadIdx.x;        // 0..98303
    const float* S = blockIdx.y ? U : W;
    __half* D = blockIdx.y ? Up : Wp;
    int pr = idx >> 6;                 // 0..1535
    int k0 = (idx & 63) * 8;           // 0..504
    int jt = pr / 96;
    int q  = pr - jt * 96;             // row within block
    int half_ = q / 48;
    int q2 = q - half_ * 48;
    int g  = q2 >> 4;
    int nn = q2 & 15;
    int col = g * 512 + jt * 32 + half_ * 16 + nn;
    int s  = k0 >> 6;
    int kc = k0 & 63;
    __align__(16) __half hi[8];
#pragma unroll
    for (int i = 0; i < 8; ++i)
        hi[i] = __float2half_rn(S[(size_t)(k0 + i) * 1536 + col]);
    size_t base = ((size_t)jt * 8 + s) * BLK_B;
    uint32_t off = SW((uint32_t)q * 128 + (uint32_t)kc * 2);
    *(uint4*)((char*)(D + base) + off) = *(const uint4*)hi;
}

__global__ __launch_bounds__(256) void pack_x16(const float* __restrict__ x, __half* __restrict__ Xp) {
    unsigned idx = blockIdx.x * 256 + threadIdx.x;   // 0..4194303
    unsigned t   = idx >> 18;
    unsigned rem = idx & 0x3FFFFu;
    unsigned m   = rem >> 6;           // GRU row 0..4095
    unsigned k0  = (rem & 63) * 8;
    unsigned bb  = m >> 5, kk = m & 31;
    const float* src = x + ((size_t)bb * T_ + (size_t)(t * SKIP_ + kk)) * 512 + k0;
    float4 v0 = *(const float4*)(src);
    float4 v1 = *(const float4*)(src + 4);
    float f[8] = {v0.x, v0.y, v0.z, v0.w, v1.x, v1.y, v1.z, v1.w};
    __align__(16) __half hi[8];
#pragma unroll
    for (int i = 0; i < 8; ++i) hi[i] = __float2half_rn(f[i]);
    unsigned mt = m >> 7, r = m & 127, s = k0 >> 6, kc = k0 & 63;
    size_t base = (((size_t)t * 32 + mt) * 8 + s) * BLK_A;
    uint32_t off = SW(r * 128 + kc * 2);
    *(uint4*)((char*)(Xp + base) + off) = *(const uint4*)hi;
}

// 12 independent-accumulator MMAs
#define DO_TERM(BT, HACC)                                              \
    do {                                                               \
        _Pragma("unroll")                                              \
        for (int mi = 0; mi < 2; ++mi)                                 \
            _Pragma("unroll")                                          \
            for (int nj = 0; nj < 2; ++nj)                             \
                mma16816(dz[mi][nj], A2[mi], &BT[0][nj * 2]);          \
        _Pragma("unroll")                                              \
        for (int mi = 0; mi < 2; ++mi)                                 \
            _Pragma("unroll")                                          \
            for (int nj = 0; nj < 2; ++nj)                             \
                mma16816(dr[mi][nj], A2[mi], &BT[1][nj * 2]);          \
        _Pragma("unroll")                                              \
        for (int mi = 0; mi < 2; ++mi)                                 \
            _Pragma("unroll")                                          \
            for (int nj = 0; nj < 2; ++nj)                             \
                mma16816(HACC[mi][nj], A2[mi], &BT[2][nj * 2]);        \
    } while (0)

#define STAGE_MMA(HACC)                                                            \
    do {                                                                           \
        _Pragma("unroll")                                                          \
        for (int k16 = 0; k16 < 4; ++k16) {                                        \
            uint32_t sa = SW(abase + k16 * 32);                                    \
            uint32_t sb2 = SW(bbase + k16 * 32);                                   \
            uint32_t A2[2][4], BH[3][4];                                           \
            ldm4(stgA + sa, A2[0]);  ldm4(stgA + sa + 16 * 128, A2[1]);            \
            ldm4(stgB + sb2, BH[0]); ldm4(stgB + sb2 + 16 * 128, BH[1]);           \
            ldm4(stgB + sb2 + 32 * 128, BH[2]);                                    \
            DO_TERM(BH, HACC);                                                     \
        }                                                                          \
    } while (0)

// ---------------- fused GRU step: TMA bulk loads, CTA tile 128x96 ----------------
__global__ __launch_bounds__(256, 2) void gru_fused(
    const __half* __restrict__ Xt,        // A blocks for this t: [mt][s]
    const __half* __restrict__ Wp,
    const __half* __restrict__ Up,
    const float* __restrict__ bias,
    const __half* __restrict__ hblk_in,   // h blocked [mt][s]
    const float* __restrict__ hprev,
    float* __restrict__ hout,
    __half* __restrict__ hblk_out,
    int first, int last)
{
    extern __shared__ __align__(128) char smem[];
    __shared__ __align__(8) uint64_t mbars[2];
    uint32_t sb  = smem_u32(smem);
    uint32_t mbu = smem_u32(mbars);

    const int tid  = threadIdx.x;
    const int lane = tid & 31;
    const int wid  = tid >> 5;
    const int wm   = wid >> 1;
    const int wn   = wid & 1;
    const int jt   = blockIdx.x;
    const int mt   = blockIdx.y;
    const int S    = first ? 8 : 16;

    const __half* Ax = Xt      + (size_t)mt * 8 * BLK_A;
    const __half* Ah = hblk_in + (size_t)mt * 8 * BLK_A;
    const __half* Bw = Wp + (size_t)jt * 8 * BLK_B;
    const __half* Bu = Up + (size_t)jt * 8 * BLK_B;

    float dz[2][2][4], dr[2][2][4], dxh[2][2][4], drh[2][2][4];
#pragma unroll
    for (int a = 0; a < 2; ++a)
#pragma unroll
        for (int b = 0; b < 2; ++b)
#pragma unroll
            for (int c = 0; c < 4; ++c) {
                dz[a][b][c] = 0.f; dr[a][b][c] = 0.f;
                dxh[a][b][c] = 0.f; drh[a][b][c] = 0.f;
            }

    if (tid == 0) { mbar_init(mbu, 1); mbar_init(mbu + 8, 1); }
    __syncthreads();

    // issue helper: stage ss -> buffer ss&1  (locals suffixed to avoid macro collisions)
    #define ISSUE(ss_)                                                             \
    do {                                                                           \
        int buf_ = (ss_) & 1;                                                      \
        uint32_t mbx_ = mbu + 8 * buf_;                                            \
        uint32_t dst_ = sb + buf_ * BUF_BYTES;                                     \
        const __half* Ap_ = ((ss_) < 8) ? (Ax + (size_t)(ss_) * BLK_A)             \
                                        : (Ah + (size_t)((ss_) - 8) * BLK_A);      \
        const __half* Bp_ = ((ss_) < 8) ? (Bw + (size_t)(ss_) * BLK_B)             \
                                        : (Bu + (size_t)((ss_) - 8) * BLK_B);      \
        mbar_expect_tx(mbx_, BUF_BYTES);                                           \
        bulk_g2s(dst_, Ap_, 16384, mbx_);                                          \
        bulk_g2s(dst_ + OFF_B, Bp_, 12288, mbx_);                                  \
    } while (0)

    if (tid == 0) { ISSUE(0); ISSUE(1); }

    // per-lane ldmatrix base offsets (pre-swizzle)
    const uint32_t abase = (uint32_t)((wm * 32 + (lane & 15)) * 128 + (lane >> 4) * 16);
    const uint32_t bbase = (uint32_t)((wn * 48 + (lane & 7) + ((lane >> 4) << 3)) * 128
                                      + ((lane >> 3) & 1) * 16);

    // ---------------- phase 0: x_t @ W ----------------
#pragma unroll 2
    for (int s = 0; s < 8; ++s) {
        mbar_wait(mbu + 8 * (s & 1), (s >> 1) & 1);
        uint32_t stgA = sb + (s & 1) * BUF_BYTES;
        uint32_t stgB = stgA + OFF_B;
        STAGE_MMA(dxh);
        __syncthreads();
        if (tid == 0 && s + 2 < S) ISSUE(s + 2);
    }

    // ---------------- phase 1: h @ U ----------------
    if (!first) {
#pragma unroll 2
        for (int s2 = 0; s2 < 8; ++s2) {
            int s = 8 + s2;
            mbar_wait(mbu + 8 * (s & 1), (s >> 1) & 1);
            uint32_t stgA = sb + (s & 1) * BUF_BYTES;
            uint32_t stgB = stgA + OFF_B;
            STAGE_MMA(drh);
            __syncthreads();
            if (tid == 0 && s + 2 < 16) ISSUE(s + 2);
        }
    }
    #undef ISSUE

    // ---------------- gate epilogue ----------------
#pragma unroll
    for (int mi = 0; mi < 2; ++mi)
#pragma unroll
        for (int rh = 0; rh < 2; ++rh) {
            int mg = mt * 128 + wm * 32 + mi * 16 + (lane >> 2) + rh * 8;
#pragma unroll
            for (int nj = 0; nj < 2; ++nj) {
                int cb   = nj * 8 + (lane & 3) * 2;
                int colh = jt * 32 + wn * 16 + cb;
                float2 hp = make_float2(0.f, 0.f);
                if (!first) hp = *(const float2*)(hprev + (size_t)mg * 512 + colh);
                float2 b0z = *(const float2*)(bias + colh);
                float2 b1z = *(const float2*)(bias + 1536 + colh);
                float2 b0r = *(const float2*)(bias + 512 + colh);
                float2 b1r = *(const float2*)(bias + 2048 + colh);
                float2 b0h = *(const float2*)(bias + 1024 + colh);
                float2 b1h = *(const float2*)(bias + 2560 + colh);
                float hpv[2] = {hp.x, hp.y};
                float b0zv[2] = {b0z.x, b0z.y}, b1zv[2] = {b1z.x, b1z.y};
                float b0rv[2] = {b0r.x, b0r.y}, b1rv[2] = {b1r.x, b1r.y};
                float b0hv[2] = {b0h.x, b0h.y}, b1hv[2] = {b1h.x, b1h.y};
                float hn[2];
#pragma unroll
                for (int cc = 0; cc < 2; ++cc) {
                    int r = rh * 2 + cc;
                    float zp  = dz[mi][nj][r] + b0zv[cc] + b1zv[cc];
                    float rp  = dr[mi][nj][r] + b0rv[cc] + b1rv[cc];
                    float xhp = dxh[mi][nj][r] + b0hv[cc];
                    float rhp = drh[mi][nj][r] + b1hv[cc];
                    float z  = sigmoidf_(zp);
                    float rg = sigmoidf_(rp);
                    float hh = fmaxf(xhp + rg * rhp, 0.f);
                    hn[cc] = z * hpv[cc] + (1.f - z) * hh;
                }
                *(float2*)(hout + (size_t)mg * 512 + colh) = make_float2(hn[0], hn[1]);
                if (!last) {
                    // blocked+swizzled h for next step's A
                    unsigned mt_h = (unsigned)mg >> 7, r2 = (unsigned)mg & 127;
                    unsigned sh = (unsigned)colh >> 6, kc = (unsigned)colh & 63;
                    size_t base = ((size_t)mt_h * 8 + sh) * BLK_A;
                    uint32_t off = SW(r2 * 128 + kc * 2);
                    *(__half2*)((char*)(hblk_out + base) + off) =
                        __halves2half2(__float2half_rn(hn[0]), __float2half_rn(hn[1]));
                }
            }
        }
}

// ---------------- host ----------------
extern "C" void kernel_launch(void* const* d_in, const int* in_sizes, int n_in,
                              void* d_out, int out_size) {
    const float* x = (const float*)d_in[0];
    const float* W = (const float*)d_in[1];
    const float* U = (const float*)d_in[2];
    const float* b = (const float*)d_in[3];
    float* out = (float*)d_out;

    __half *Xp, *Wp, *Up, *Hp0;
    float *Hf0;
    cudaGetSymbolAddress((void**)&Xp, g_xp16);
    cudaGetSymbolAddress((void**)&Wp, g_wp16);
    cudaGetSymbolAddress((void**)&Up, g_up16);
    cudaGetSymbolAddress((void**)&Hf0, g_hf);
    cudaGetSymbolAddress((void**)&Hp0, g_hp16);
    float*  Hf[2] = {Hf0, Hf0 + (size_t)NSEQ * 512};
    __half* Hp[2] = {Hp0, Hp0 + (size_t)32 * 8 * BLK_A};

    static int smem_set = 0;
    if (!smem_set) {
        cudaFuncSetAttribute(gru_fused, cudaFuncAttributeMaxDynamicSharedMemorySize, SMEM_BYTES);
        smem_set = 1;
    }

    pack_wu16<<<dim3(384, 2), 256>>>(W, U, Wp, Up);
    pack_x16<<<16384, 256>>>(x, Xp);

    for (int t = 0; t < PT_; ++t) {
        const __half* Xt   = Xp + (size_t)t * 32 * 8 * BLK_A;
        const __half* Ahp  = Hp[(t + 1) & 1];
        const float* hprev = Hf[(t + 1) & 1];
        float* ho = (t == PT_ - 1) ? out : Hf[t & 1];
        gru_fused<<<dim3(16, 32), 256, SMEM_BYTES>>>(
            Xt, Wp, Up, b, Ahp, hprev, ho, Hp[t & 1],
            t == 0 ? 1 : 0, t == PT_ - 1 ? 1 : 0);
    }
    (void)in_sizes; (void)n_in; (void)out_size;
}